// round 2
// baseline (speedup 1.0000x reference)
#include <cuda_runtime.h>
#include <cuda_bf16.h>
#include <cstdint>

#define NN 50000
#define EE 800000
#define PP 65536

// ---------------- device scratch (static, no allocation) ----------------
__device__ int    g_cnt[NN];
__device__ int    g_cur[NN];
__device__ int    g_off[NN + 1];
__device__ float  g_deg_norm[NN];
__device__ int    g_src_s[EE];
__device__ float  g_w_s[EE];
__device__ float  g_fcat[(size_t)NN * 512];   // concat buffer [N,512]
__device__ float  g_h[(size_t)NN * 128];      // layer output  [N,128]
__device__ float4 g_rs_a[(size_t)NN * 32];    // scaled features ping
__device__ float4 g_rs_b[(size_t)NN * 32];    // scaled features pong

// ---------------- CSR build ----------------
__global__ void zero_k() {
    int i = blockIdx.x * blockDim.x + threadIdx.x;
    if (i < NN) { g_cnt[i] = 0; g_cur[i] = 0; }
}

__global__ void count_k(const int* __restrict__ dst) {
    int e = blockIdx.x * blockDim.x + threadIdx.x;
    if (e < EE) atomicAdd(&g_cnt[dst[e]], 1);
}

__global__ void degnorm_k() {
    int i = blockIdx.x * blockDim.x + threadIdx.x;
    if (i < NN) g_deg_norm[i] = rsqrtf(fmaxf((float)g_cnt[i], 1.0f));
}

// single-block exclusive scan of g_cnt -> g_off
__global__ void scan_k() {
    __shared__ int sh[1024];
    int carry = 0;
    for (int base = 0; base < NN; base += 1024) {
        int i = base + threadIdx.x;
        int v = (i < NN) ? g_cnt[i] : 0;
        sh[threadIdx.x] = v;
        __syncthreads();
        #pragma unroll
        for (int ofs = 1; ofs < 1024; ofs <<= 1) {
            int t = (threadIdx.x >= ofs) ? sh[threadIdx.x - ofs] : 0;
            __syncthreads();
            sh[threadIdx.x] += t;
            __syncthreads();
        }
        if (i < NN) g_off[i] = carry + sh[threadIdx.x] - v;
        carry += sh[1023];
        __syncthreads();
    }
    if (threadIdx.x == 0) g_off[NN] = carry;
}

__global__ void scatter_k(const int* __restrict__ src, const int* __restrict__ dst,
                          const float* __restrict__ w) {
    int e = blockIdx.x * blockDim.x + threadIdx.x;
    if (e >= EE) return;
    int d = dst[e];
    int p = g_off[d] + atomicAdd(&g_cur[d], 1);
    g_src_s[p] = src[e];
    g_w_s[p]   = w[e];
}

// ---------------- layer prep: fcat[:,0:128] = in ; rs = in * deg_norm ----------------
__global__ void prep_k(const float* __restrict__ in) {
    int idx = blockIdx.x * blockDim.x + threadIdx.x;   // N*32
    if (idx >= NN * 32) return;
    int n = idx >> 5, q = idx & 31;
    float4 v = *reinterpret_cast<const float4*>(&in[(size_t)n * 128 + q * 4]);
    *reinterpret_cast<float4*>(&g_fcat[(size_t)n * 512 + q * 4]) = v;
    float dn = g_deg_norm[n];
    float4 r = make_float4(v.x * dn, v.y * dn, v.z * dn, v.w * dn);
    g_rs_a[idx] = r;
}

// ---------------- hop: out[n] = dn[n] * sum_{e in CSR[n]} w_e * rs[src_e] ----------------
__global__ void hop_k(const float4* __restrict__ rs_in, float4* __restrict__ rs_out,
                      int colofs) {
    int gid = blockIdx.x * blockDim.x + threadIdx.x;
    int node = gid >> 5;
    int lane = gid & 31;
    if (node >= NN) return;
    int beg = g_off[node], end = g_off[node + 1];
    float4 acc = make_float4(0.f, 0.f, 0.f, 0.f);
    int e = beg;
    // unroll by 2 for MLP
    for (; e + 1 < end; e += 2) {
        int   s0 = g_src_s[e];     float w0 = g_w_s[e];
        int   s1 = g_src_s[e + 1]; float w1 = g_w_s[e + 1];
        float4 v0 = rs_in[(size_t)s0 * 32 + lane];
        float4 v1 = rs_in[(size_t)s1 * 32 + lane];
        acc.x = fmaf(w0, v0.x, acc.x); acc.y = fmaf(w0, v0.y, acc.y);
        acc.z = fmaf(w0, v0.z, acc.z); acc.w = fmaf(w0, v0.w, acc.w);
        acc.x = fmaf(w1, v1.x, acc.x); acc.y = fmaf(w1, v1.y, acc.y);
        acc.z = fmaf(w1, v1.z, acc.z); acc.w = fmaf(w1, v1.w, acc.w);
    }
    if (e < end) {
        int s = g_src_s[e]; float w = g_w_s[e];
        float4 v = rs_in[(size_t)s * 32 + lane];
        acc.x = fmaf(w, v.x, acc.x); acc.y = fmaf(w, v.y, acc.y);
        acc.z = fmaf(w, v.z, acc.z); acc.w = fmaf(w, v.w, acc.w);
    }
    float dn = g_deg_norm[node];
    float4 f = make_float4(dn * acc.x, dn * acc.y, dn * acc.z, dn * acc.w);
    *reinterpret_cast<float4*>(&g_fcat[(size_t)node * 512 + colofs + lane * 4]) = f;
    float4 r = make_float4(dn * f.x, dn * f.y, dn * f.z, dn * f.w);
    rs_out[(size_t)node * 32 + lane] = r;
}

// ---------------- GEMM: C[M,BN] = fcat[M,512] @ B[512,BN] + bias (opt relu) ----------------
template <int BN, int TN, bool RELU>
__global__ __launch_bounds__(256)
void gemm_k(const float* __restrict__ B, const float* __restrict__ bias,
            float* __restrict__ C, int M) {
    constexpr int BM = 128, BK = 16, TM = 8;
    __shared__ float As[BK][BM];
    __shared__ float Bs[BK][BN];
    const float* A = g_fcat;
    int t = threadIdx.x;
    int tx = t & 15, ty = t >> 4;
    int row0 = blockIdx.x * BM;
    float acc[TM][TN];
    #pragma unroll
    for (int i = 0; i < TM; i++)
        #pragma unroll
        for (int j = 0; j < TN; j++) acc[i][j] = 0.f;

    for (int k0 = 0; k0 < 512; k0 += BK) {
        // load A tile (transposed into shared): 512 float4s, 2 per thread
        #pragma unroll
        for (int l = 0; l < 2; l++) {
            int idx = t + l * 256;
            int r = idx >> 2, c4 = idx & 3;
            float4 v = make_float4(0.f, 0.f, 0.f, 0.f);
            int gr = row0 + r;
            if (gr < M)
                v = *reinterpret_cast<const float4*>(&A[(size_t)gr * 512 + k0 + c4 * 4]);
            As[c4 * 4 + 0][r] = v.x;
            As[c4 * 4 + 1][r] = v.y;
            As[c4 * 4 + 2][r] = v.z;
            As[c4 * 4 + 3][r] = v.w;
        }
        // load B tile
        constexpr int NB4 = BK * BN / 4;
        #pragma unroll
        for (int idx = t; idx < NB4; idx += 256) {
            int r = idx / (BN / 4), c4 = idx % (BN / 4);
            float4 v = *reinterpret_cast<const float4*>(&B[(size_t)(k0 + r) * BN + c4 * 4]);
            *reinterpret_cast<float4*>(&Bs[r][c4 * 4]) = v;
        }
        __syncthreads();
        #pragma unroll
        for (int k = 0; k < BK; k++) {
            float a[TM], b[TN];
            #pragma unroll
            for (int i = 0; i < TM; i++) a[i] = As[k][ty * TM + i];
            #pragma unroll
            for (int j = 0; j < TN; j++) b[j] = Bs[k][tx * TN + j];
            #pragma unroll
            for (int i = 0; i < TM; i++)
                #pragma unroll
                for (int j = 0; j < TN; j++) acc[i][j] = fmaf(a[i], b[j], acc[i][j]);
        }
        __syncthreads();
    }
    float bv[TN];
    #pragma unroll
    for (int j = 0; j < TN; j++) bv[j] = bias[tx * TN + j];
    #pragma unroll
    for (int i = 0; i < TM; i++) {
        int gr = row0 + ty * TM + i;
        if (gr >= M) continue;
        #pragma unroll
        for (int j = 0; j < TN; j++) {
            float v = acc[i][j] + bv[j];
            if (RELU) v = fmaxf(v, 0.f);
            C[(size_t)gr * BN + tx * TN + j] = v;
        }
    }
}

// ---------------- predictor: out[p] = MLP(h[a]*h[b]) ----------------
__global__ __launch_bounds__(256)
void pred_k(const int* __restrict__ sa, const int* __restrict__ sb,
            const float* __restrict__ h,
            const float* __restrict__ P1, const float* __restrict__ pb1,
            const float* __restrict__ P2, const float* __restrict__ pb2,
            const float* __restrict__ P3, const float* __restrict__ pb3,
            float* __restrict__ out) {
    __shared__ float sP1[64 * 32];
    __shared__ float sP2[32 * 16];
    __shared__ float sP3[16];
    __shared__ float sb1[32];
    __shared__ float sb2[16];
    __shared__ float sb3;
    __shared__ float sz[8][64];
    int t = threadIdx.x;
    for (int i = t; i < 2048; i += 256) sP1[i] = P1[i];
    for (int i = t; i < 512; i += 256) sP2[i] = P2[i];
    if (t < 16) sP3[t] = P3[t];
    if (t < 32) sb1[t] = pb1[t];
    if (t < 16) sb2[t] = pb2[t];
    if (t == 0) sb3 = pb3[0];
    __syncthreads();
    int w = t >> 5, lane = t & 31;
    int gw = blockIdx.x * 8 + w;
    int nwarps = gridDim.x * 8;
    for (int p = gw; p < PP; p += nwarps) {
        int a = sa[p], b = sb[p];
        float2 ha = *reinterpret_cast<const float2*>(&h[(size_t)a * 64 + lane * 2]);
        float2 hb = *reinterpret_cast<const float2*>(&h[(size_t)b * 64 + lane * 2]);
        sz[w][lane * 2]     = ha.x * hb.x;
        sz[w][lane * 2 + 1] = ha.y * hb.y;
        __syncwarp();
        float acc = sb1[lane];
        #pragma unroll
        for (int i = 0; i < 64; i++) acc = fmaf(sz[w][i], sP1[i * 32 + lane], acc);
        acc = acc > 0.f ? acc : 0.2f * acc;
        __syncwarp();
        sz[w][lane] = acc;
        __syncwarp();
        float acc2 = 0.f;
        if (lane < 16) {
            acc2 = sb2[lane];
            #pragma unroll
            for (int i = 0; i < 32; i++) acc2 = fmaf(sz[w][i], sP2[i * 16 + lane], acc2);
            acc2 = acc2 > 0.f ? acc2 : 0.2f * acc2;
        }
        __syncwarp();
        if (lane < 16) sz[w][lane] = acc2 * sP3[lane];
        __syncwarp();
        if (lane == 0) {
            float s = sb3;
            #pragma unroll
            for (int i = 0; i < 16; i++) s += sz[w][i];
            out[p] = s;
        }
        __syncwarp();
    }
}

// ---------------- host launcher ----------------
extern "C" void kernel_launch(void* const* d_in, const int* in_sizes, int n_in,
                              void* d_out, int out_size) {
    const float* x       = (const float*)d_in[0];
    const int*   src     = (const int*)d_in[1];
    const int*   dst     = (const int*)d_in[2];
    const float* w_edge  = (const float*)d_in[3];
    const int*   pos_src = (const int*)d_in[4];
    const int*   pos_dst = (const int*)d_in[5];
    const int*   neg_src = (const int*)d_in[6];
    const int*   neg_dst = (const int*)d_in[7];
    const float* W1 = (const float*)d_in[8];
    const float* b1 = (const float*)d_in[9];
    const float* W2 = (const float*)d_in[10];
    const float* b2 = (const float*)d_in[11];
    const float* W3 = (const float*)d_in[12];
    const float* b3 = (const float*)d_in[13];
    const float* P1 = (const float*)d_in[14];
    const float* pb1 = (const float*)d_in[15];
    const float* P2 = (const float*)d_in[16];
    const float* pb2 = (const float*)d_in[17];
    const float* P3 = (const float*)d_in[18];
    const float* pb3 = (const float*)d_in[19];

    float* out = (float*)d_out;
    float* out_pos = out;                 // [P]
    float* out_neg = out + PP;            // [P]
    float* out_h   = out + 2 * PP;        // [N,64]

    // device-global pointers (host-side symbol lookup; no allocation)
    static float4* rs_a = nullptr;
    static float4* rs_b = nullptr;
    static float*  hbuf = nullptr;
    if (!rs_a) {
        cudaGetSymbolAddress((void**)&rs_a, g_rs_a);
        cudaGetSymbolAddress((void**)&rs_b, g_rs_b);
        cudaGetSymbolAddress((void**)&hbuf, g_h);
    }

    const int TB = 256;
    int nb_N  = (NN + TB - 1) / TB;
    int nb_E  = (EE + TB - 1) / TB;
    int nb_hop = (NN * 32 + TB - 1) / TB;
    int nb_gemm = (NN + 127) / 128;

    // CSR build
    zero_k<<<nb_N, TB>>>();
    count_k<<<nb_E, TB>>>(dst);
    degnorm_k<<<nb_N, TB>>>();
    scan_k<<<1, 1024>>>();
    scatter_k<<<nb_E, TB>>>(src, dst, w_edge);

    // ---- layer 1 ----
    prep_k<<<nb_hop, TB>>>(x);
    hop_k<<<nb_hop, TB>>>(rs_a, rs_b, 128);
    hop_k<<<nb_hop, TB>>>(rs_b, rs_a, 256);
    hop_k<<<nb_hop, TB>>>(rs_a, rs_b, 384);
    gemm_k<128, 8, true><<<nb_gemm, 256>>>(W1, b1, hbuf, NN);

    // ---- layer 2 ----
    prep_k<<<nb_hop, TB>>>(hbuf);
    hop_k<<<nb_hop, TB>>>(rs_a, rs_b, 128);
    hop_k<<<nb_hop, TB>>>(rs_b, rs_a, 256);
    hop_k<<<nb_hop, TB>>>(rs_a, rs_b, 384);
    gemm_k<128, 8, true><<<nb_gemm, 256>>>(W2, b2, hbuf, NN);

    // ---- layer 3 ----
    prep_k<<<nb_hop, TB>>>(hbuf);
    hop_k<<<nb_hop, TB>>>(rs_a, rs_b, 128);
    hop_k<<<nb_hop, TB>>>(rs_b, rs_a, 256);
    hop_k<<<nb_hop, TB>>>(rs_a, rs_b, 384);
    gemm_k<64, 4, false><<<nb_gemm, 256>>>(W3, b3, out_h, NN);

    // ---- predictor ----
    pred_k<<<512, 256>>>(pos_src, pos_dst, out_h, P1, pb1, P2, pb2, P3, pb3, out_pos);
    pred_k<<<512, 256>>>(neg_src, neg_dst, out_h, P1, pb1, P2, pb2, P3, pb3, out_neg);
}

// round 3
// speedup vs baseline: 1.1239x; 1.1239x over previous
#include <cuda_runtime.h>
#include <cuda_bf16.h>
#include <cstdint>

#define NN 50000
#define EE 800000
#define PP 65536
#define NCHUNK ((NN + 1023) / 1024)

// ---------------- device scratch (static, no allocation) ----------------
__device__ int    g_cnt[NN];
__device__ int    g_cur[NN];
__device__ int    g_off[NN + 1];
__device__ int    g_part[NCHUNK];
__device__ float  g_deg_norm[NN];
__device__ int    g_src_s[EE];
__device__ float  g_w_s[EE];
__device__ float  g_fcat[(size_t)NN * 512];   // concat buffer [N,512]
__device__ float  g_h[(size_t)NN * 128];      // layer output  [N,128]
__device__ float4 g_rs_a[(size_t)NN * 32];    // scaled features ping
__device__ float4 g_rs_b[(size_t)NN * 32];    // scaled features pong

// ---------------- CSR build ----------------
__global__ void zero_k() {
    int i = blockIdx.x * blockDim.x + threadIdx.x;
    if (i < NN) { g_cnt[i] = 0; g_cur[i] = 0; }
}

__global__ void count_k(const int* __restrict__ dst) {
    int e = blockIdx.x * blockDim.x + threadIdx.x;
    if (e < EE) atomicAdd(&g_cnt[dst[e]], 1);
}

__global__ void degnorm_k() {
    int i = blockIdx.x * blockDim.x + threadIdx.x;
    if (i < NN) g_deg_norm[i] = rsqrtf(fmaxf((float)g_cnt[i], 1.0f));
}

// scan pass 1: per-1024-chunk exclusive scan via warp shuffles; chunk sums to g_part
__global__ void scan1_k() {
    __shared__ int wsum[32];
    int lane = threadIdx.x & 31, wid = threadIdx.x >> 5;
    int i = blockIdx.x * 1024 + threadIdx.x;
    int v = (i < NN) ? g_cnt[i] : 0;
    int s = v;
    #pragma unroll
    for (int o = 1; o < 32; o <<= 1) {
        int n = __shfl_up_sync(0xffffffffu, s, o);
        if (lane >= o) s += n;
    }
    if (lane == 31) wsum[wid] = s;
    __syncthreads();
    if (wid == 0) {
        int t = wsum[lane];
        #pragma unroll
        for (int o = 1; o < 32; o <<= 1) {
            int n = __shfl_up_sync(0xffffffffu, t, o);
            if (lane >= o) t += n;
        }
        wsum[lane] = t;
    }
    __syncthreads();
    int base = (wid > 0) ? wsum[wid - 1] : 0;
    if (i < NN) g_off[i] = base + s - v;       // exclusive within chunk
    if (threadIdx.x == 1023) g_part[blockIdx.x] = base + s;
}

// scan pass 2: serial scan of NCHUNK partials (tiny)
__global__ void scan2_k() {
    int run = 0;
    for (int c = 0; c < NCHUNK; c++) { int v = g_part[c]; g_part[c] = run; run += v; }
    g_off[NN] = run;
}

// scan pass 3: add chunk offsets
__global__ void scan3_k() {
    int i = blockIdx.x * 1024 + threadIdx.x;
    if (i < NN) g_off[i] += g_part[blockIdx.x];
}

__global__ void scatter_k(const int* __restrict__ src, const int* __restrict__ dst,
                          const float* __restrict__ w) {
    int e = blockIdx.x * blockDim.x + threadIdx.x;
    if (e >= EE) return;
    int d = dst[e];
    int p = g_off[d] + atomicAdd(&g_cur[d], 1);
    g_src_s[p] = src[e];
    g_w_s[p]   = w[e];
}

// ---------------- layer prep: fcat[:,0:128] = in ; rs = in * deg_norm ----------------
__global__ void prep_k(const float* __restrict__ in) {
    int idx = blockIdx.x * blockDim.x + threadIdx.x;   // N*32
    if (idx >= NN * 32) return;
    int n = idx >> 5, q = idx & 31;
    float4 v = *reinterpret_cast<const float4*>(&in[(size_t)n * 128 + q * 4]);
    *reinterpret_cast<float4*>(&g_fcat[(size_t)n * 512 + q * 4]) = v;
    float dn = g_deg_norm[n];
    float4 r = make_float4(v.x * dn, v.y * dn, v.z * dn, v.w * dn);
    g_rs_a[idx] = r;
}

// ---------------- hop: out[n] = dn[n] * sum_{e in CSR[n]} w_e * rs[src_e] ----------------
__global__ void hop_k(const float4* __restrict__ rs_in, float4* __restrict__ rs_out,
                      int colofs) {
    int gid = blockIdx.x * blockDim.x + threadIdx.x;
    int node = gid >> 5;
    int lane = gid & 31;
    if (node >= NN) return;
    int beg = g_off[node], end = g_off[node + 1];
    float4 acc = make_float4(0.f, 0.f, 0.f, 0.f);
    int e = beg;
    for (; e + 1 < end; e += 2) {
        int   s0 = g_src_s[e];     float w0 = g_w_s[e];
        int   s1 = g_src_s[e + 1]; float w1 = g_w_s[e + 1];
        float4 v0 = rs_in[(size_t)s0 * 32 + lane];
        float4 v1 = rs_in[(size_t)s1 * 32 + lane];
        acc.x = fmaf(w0, v0.x, acc.x); acc.y = fmaf(w0, v0.y, acc.y);
        acc.z = fmaf(w0, v0.z, acc.z); acc.w = fmaf(w0, v0.w, acc.w);
        acc.x = fmaf(w1, v1.x, acc.x); acc.y = fmaf(w1, v1.y, acc.y);
        acc.z = fmaf(w1, v1.z, acc.z); acc.w = fmaf(w1, v1.w, acc.w);
    }
    if (e < end) {
        int s = g_src_s[e]; float w = g_w_s[e];
        float4 v = rs_in[(size_t)s * 32 + lane];
        acc.x = fmaf(w, v.x, acc.x); acc.y = fmaf(w, v.y, acc.y);
        acc.z = fmaf(w, v.z, acc.z); acc.w = fmaf(w, v.w, acc.w);
    }
    float dn = g_deg_norm[node];
    float4 f = make_float4(dn * acc.x, dn * acc.y, dn * acc.z, dn * acc.w);
    *reinterpret_cast<float4*>(&g_fcat[(size_t)node * 512 + colofs + lane * 4]) = f;
    float4 r = make_float4(dn * f.x, dn * f.y, dn * f.z, dn * f.w);
    rs_out[(size_t)node * 32 + lane] = r;
}

// ---------------- f32x2 helpers ----------------
__device__ __forceinline__ unsigned long long pack_dup(float a) {
    unsigned long long r;
    asm("mov.b64 %0, {%1, %1};" : "=l"(r) : "f"(a));
    return r;
}
__device__ __forceinline__ void ffma2(unsigned long long& acc, unsigned long long a,
                                      unsigned long long b) {
    asm("fma.rn.f32x2 %0, %1, %2, %0;" : "+l"(acc) : "l"(a), "l"(b));
}

// ---------------- GEMM: C[M,BN] = fcat[M,512] @ B[512,BN] + bias (opt relu) ----------------
// FFMA2 (f32x2) inner loop: 2 fp32 FMAs per issued instruction.
template <int BN, int TN, bool RELU>
__global__ __launch_bounds__(256)
void gemm_k(const float* __restrict__ B, const float* __restrict__ bias,
            float* __restrict__ C, int M) {
    constexpr int BM = 128, BK = 16, TM = 8;
    constexpr int TN2 = TN / 2;
    __shared__ __align__(16) float As[BK][BM];
    __shared__ __align__(16) float Bs[BK][BN];
    const float* A = g_fcat;
    int t = threadIdx.x;
    int tx = t & 15, ty = t >> 4;
    int row0 = blockIdx.x * BM;
    unsigned long long acc2[TM][TN2];
    #pragma unroll
    for (int i = 0; i < TM; i++)
        #pragma unroll
        for (int j = 0; j < TN2; j++) acc2[i][j] = 0ull;

    for (int k0 = 0; k0 < 512; k0 += BK) {
        #pragma unroll
        for (int l = 0; l < 2; l++) {
            int idx = t + l * 256;
            int r = idx >> 2, c4 = idx & 3;
            float4 v = make_float4(0.f, 0.f, 0.f, 0.f);
            int gr = row0 + r;
            if (gr < M)
                v = *reinterpret_cast<const float4*>(&A[(size_t)gr * 512 + k0 + c4 * 4]);
            As[c4 * 4 + 0][r] = v.x;
            As[c4 * 4 + 1][r] = v.y;
            As[c4 * 4 + 2][r] = v.z;
            As[c4 * 4 + 3][r] = v.w;
        }
        constexpr int NB4 = BK * BN / 4;
        #pragma unroll
        for (int idx = t; idx < NB4; idx += 256) {
            int r = idx / (BN / 4), c4 = idx % (BN / 4);
            float4 v = *reinterpret_cast<const float4*>(&B[(size_t)(k0 + r) * BN + c4 * 4]);
            *reinterpret_cast<float4*>(&Bs[r][c4 * 4]) = v;
        }
        __syncthreads();
        #pragma unroll
        for (int k = 0; k < BK; k++) {
            unsigned long long a2[TM], b2[TN2];
            #pragma unroll
            for (int i = 0; i < TM; i++) a2[i] = pack_dup(As[k][ty * TM + i]);
            #pragma unroll
            for (int j = 0; j < TN2; j++)
                b2[j] = *reinterpret_cast<const unsigned long long*>(&Bs[k][tx * TN + j * 2]);
            #pragma unroll
            for (int i = 0; i < TM; i++)
                #pragma unroll
                for (int j = 0; j < TN2; j++) ffma2(acc2[i][j], a2[i], b2[j]);
        }
        __syncthreads();
    }
    float bv[TN];
    #pragma unroll
    for (int j = 0; j < TN; j++) bv[j] = bias[tx * TN + j];
    #pragma unroll
    for (int i = 0; i < TM; i++) {
        int gr = row0 + ty * TM + i;
        if (gr >= M) continue;
        #pragma unroll
        for (int j = 0; j < TN2; j++) {
            unsigned int lo, hi;
            asm("mov.b64 {%0, %1}, %2;" : "=r"(lo), "=r"(hi) : "l"(acc2[i][j]));
            float v0 = __uint_as_float(lo) + bv[j * 2];
            float v1 = __uint_as_float(hi) + bv[j * 2 + 1];
            if (RELU) { v0 = fmaxf(v0, 0.f); v1 = fmaxf(v1, 0.f); }
            float2 o = make_float2(v0, v1);
            *reinterpret_cast<float2*>(&C[(size_t)gr * BN + tx * TN + j * 2]) = o;
        }
    }
}

// ---------------- predictor: out[p] = MLP(h[a]*h[b]) for pos then neg ----------------
__global__ __launch_bounds__(256)
void pred_k(const int* __restrict__ pa, const int* __restrict__ pb,
            const int* __restrict__ na, const int* __restrict__ nb,
            const float* __restrict__ h,
            const float* __restrict__ P1, const float* __restrict__ pb1,
            const float* __restrict__ P2, const float* __restrict__ pb2,
            const float* __restrict__ P3, const float* __restrict__ pb3,
            float* __restrict__ out) {
    __shared__ float sP1[64 * 32];
    __shared__ float sP2[32 * 16];
    __shared__ float sP3[16];
    __shared__ float sb1[32];
    __shared__ float sb2[16];
    __shared__ float sb3;
    __shared__ float sz[8][64];
    int t = threadIdx.x;
    for (int i = t; i < 2048; i += 256) sP1[i] = P1[i];
    for (int i = t; i < 512; i += 256) sP2[i] = P2[i];
    if (t < 16) sP3[t] = P3[t];
    if (t < 32) sb1[t] = pb1[t];
    if (t < 16) sb2[t] = pb2[t];
    if (t == 0) sb3 = pb3[0];
    __syncthreads();
    int w = t >> 5, lane = t & 31;
    int gw = blockIdx.x * 8 + w;
    int nwarps = gridDim.x * 8;
    for (int p = gw; p < 2 * PP; p += nwarps) {
        int a, b;
        if (p < PP) { a = pa[p]; b = pb[p]; }
        else        { a = na[p - PP]; b = nb[p - PP]; }
        float2 ha = *reinterpret_cast<const float2*>(&h[(size_t)a * 64 + lane * 2]);
        float2 hb = *reinterpret_cast<const float2*>(&h[(size_t)b * 64 + lane * 2]);
        sz[w][lane * 2]     = ha.x * hb.x;
        sz[w][lane * 2 + 1] = ha.y * hb.y;
        __syncwarp();
        float acc = sb1[lane];
        #pragma unroll
        for (int i = 0; i < 64; i++) acc = fmaf(sz[w][i], sP1[i * 32 + lane], acc);
        acc = acc > 0.f ? acc : 0.2f * acc;
        __syncwarp();
        sz[w][lane] = acc;
        __syncwarp();
        float acc2 = 0.f;
        if (lane < 16) {
            acc2 = sb2[lane];
            #pragma unroll
            for (int i = 0; i < 32; i++) acc2 = fmaf(sz[w][i], sP2[i * 16 + lane], acc2);
            acc2 = acc2 > 0.f ? acc2 : 0.2f * acc2;
        }
        __syncwarp();
        if (lane < 16) sz[w][lane] = acc2 * sP3[lane];
        __syncwarp();
        if (lane == 0) {
            float s = sb3;
            #pragma unroll
            for (int i = 0; i < 16; i++) s += sz[w][i];
            out[p] = s;
        }
        __syncwarp();
    }
}

// ---------------- host launcher ----------------
extern "C" void kernel_launch(void* const* d_in, const int* in_sizes, int n_in,
                              void* d_out, int out_size) {
    const float* x       = (const float*)d_in[0];
    const int*   src     = (const int*)d_in[1];
    const int*   dst     = (const int*)d_in[2];
    const float* w_edge  = (const float*)d_in[3];
    const int*   pos_src = (const int*)d_in[4];
    const int*   pos_dst = (const int*)d_in[5];
    const int*   neg_src = (const int*)d_in[6];
    const int*   neg_dst = (const int*)d_in[7];
    const float* W1 = (const float*)d_in[8];
    const float* b1 = (const float*)d_in[9];
    const float* W2 = (const float*)d_in[10];
    const float* b2 = (const float*)d_in[11];
    const float* W3 = (const float*)d_in[12];
    const float* b3 = (const float*)d_in[13];
    const float* P1 = (const float*)d_in[14];
    const float* pb1 = (const float*)d_in[15];
    const float* P2 = (const float*)d_in[16];
    const float* pb2 = (const float*)d_in[17];
    const float* P3 = (const float*)d_in[18];
    const float* pb3 = (const float*)d_in[19];

    float* out = (float*)d_out;
    float* out_pos = out;                 // [P] then [P] then [N,64]
    float* out_h   = out + 2 * PP;

    static float4* rs_a = nullptr;
    static float4* rs_b = nullptr;
    static float*  hbuf = nullptr;
    if (!rs_a) {
        cudaGetSymbolAddress((void**)&rs_a, g_rs_a);
        cudaGetSymbolAddress((void**)&rs_b, g_rs_b);
        cudaGetSymbolAddress((void**)&hbuf, g_h);
    }

    const int TB = 256;
    int nb_N  = (NN + TB - 1) / TB;
    int nb_E  = (EE + TB - 1) / TB;
    int nb_hop = (NN * 32 + TB - 1) / TB;
    int nb_gemm = (NN + 127) / 128;

    // CSR build
    zero_k<<<nb_N, TB>>>();
    count_k<<<nb_E, TB>>>(dst);
    degnorm_k<<<nb_N, TB>>>();
    scan1_k<<<NCHUNK, 1024>>>();
    scan2_k<<<1, 1>>>();
    scan3_k<<<NCHUNK, 1024>>>();
    scatter_k<<<nb_E, TB>>>(src, dst, w_edge);

    // ---- layer 1 ----
    prep_k<<<nb_hop, TB>>>(x);
    hop_k<<<nb_hop, TB>>>(rs_a, rs_b, 128);
    hop_k<<<nb_hop, TB>>>(rs_b, rs_a, 256);
    hop_k<<<nb_hop, TB>>>(rs_a, rs_b, 384);
    gemm_k<128, 8, true><<<nb_gemm, 256>>>(W1, b1, hbuf, NN);

    // ---- layer 2 ----
    prep_k<<<nb_hop, TB>>>(hbuf);
    hop_k<<<nb_hop, TB>>>(rs_a, rs_b, 128);
    hop_k<<<nb_hop, TB>>>(rs_b, rs_a, 256);
    hop_k<<<nb_hop, TB>>>(rs_a, rs_b, 384);
    gemm_k<128, 8, true><<<nb_gemm, 256>>>(W2, b2, hbuf, NN);

    // ---- layer 3 ----
    prep_k<<<nb_hop, TB>>>(hbuf);
    hop_k<<<nb_hop, TB>>>(rs_a, rs_b, 128);
    hop_k<<<nb_hop, TB>>>(rs_b, rs_a, 256);
    hop_k<<<nb_hop, TB>>>(rs_a, rs_b, 384);
    gemm_k<64, 4, false><<<nb_gemm, 256>>>(W3, b3, out_h, NN);

    // ---- predictor (pos+neg fused) ----
    pred_k<<<1024, 256>>>(pos_src, pos_dst, neg_src, neg_dst, out_h,
                          P1, pb1, P2, pb2, P3, pb3, out_pos);
}

// round 9
// speedup vs baseline: 1.4759x; 1.3131x over previous
#include <cuda_runtime.h>
#include <cuda_bf16.h>
#include <cstdint>

#define NN 50000
#define EE 800000
#define PP 65536
#define NCHUNK ((NN + 1023) / 1024)

// ================= device scratch =================
__device__ int    g_cnt[NN];
__device__ int    g_cur[NN];
__device__ int    g_off[NN + 1];
__device__ int    g_part[NCHUNK];
__device__ float  g_deg_norm[NN];
__device__ int    g_src_s[EE];
__device__ float  g_w_s[EE];
__device__ __nv_bfloat16 g_fh[(size_t)NN * 512];   // concat hi [N,512]
__device__ __nv_bfloat16 g_fl[(size_t)NN * 512];   // concat lo [N,512]
__device__ float  g_h[(size_t)NN * 128];           // layer output [N,128]
__device__ float4 g_rs_a[(size_t)NN * 32];
__device__ float4 g_rs_b[(size_t)NN * 32];
__device__ __nv_bfloat16 g_wh[3][128 * 512];       // W^T hi per layer [n,k]
__device__ __nv_bfloat16 g_wl[3][128 * 512];       // W^T lo per layer [n,k]

// ================= small helpers =================
__device__ __forceinline__ uint32_t smem_u32(const void* p) {
    uint32_t a;
    asm("{ .reg .u64 t; cvta.to.shared.u64 t, %1; cvt.u32.u64 %0, t; }" : "=r"(a) : "l"(p));
    return a;
}
__device__ __forceinline__ void ldsm4(uint32_t& r0, uint32_t& r1, uint32_t& r2,
                                      uint32_t& r3, uint32_t addr) {
    asm volatile("ldmatrix.sync.aligned.m8n8.x4.shared.b16 {%0,%1,%2,%3}, [%4];"
                 : "=r"(r0), "=r"(r1), "=r"(r2), "=r"(r3) : "r"(addr));
}
__device__ __forceinline__ void mma16816(float* c, const uint32_t* a, const uint32_t* b) {
    asm volatile(
        "mma.sync.aligned.m16n8k16.row.col.f32.bf16.bf16.f32 "
        "{%0,%1,%2,%3}, {%4,%5,%6,%7}, {%8,%9}, {%0,%1,%2,%3};"
        : "+f"(c[0]), "+f"(c[1]), "+f"(c[2]), "+f"(c[3])
        : "r"(a[0]), "r"(a[1]), "r"(a[2]), "r"(a[3]), "r"(b[0]), "r"(b[1]));
}

// ================= CSR build =================
__global__ void zero_k() {
    int i = blockIdx.x * blockDim.x + threadIdx.x;
    if (i < NN) { g_cnt[i] = 0; g_cur[i] = 0; }
}
__global__ void count_k(const int* __restrict__ dst) {
    int e = blockIdx.x * blockDim.x + threadIdx.x;
    if (e < EE) atomicAdd(&g_cnt[dst[e]], 1);
}
__global__ void degnorm_k() {
    int i = blockIdx.x * blockDim.x + threadIdx.x;
    if (i < NN) g_deg_norm[i] = rsqrtf(fmaxf((float)g_cnt[i], 1.0f));
}
__global__ void scan1_k() {
    __shared__ int wsum[32];
    int lane = threadIdx.x & 31, wid = threadIdx.x >> 5;
    int i = blockIdx.x * 1024 + threadIdx.x;
    int v = (i < NN) ? g_cnt[i] : 0;
    int s = v;
    #pragma unroll
    for (int o = 1; o < 32; o <<= 1) {
        int n = __shfl_up_sync(0xffffffffu, s, o);
        if (lane >= o) s += n;
    }
    if (lane == 31) wsum[wid] = s;
    __syncthreads();
    if (wid == 0) {
        int t = wsum[lane];
        #pragma unroll
        for (int o = 1; o < 32; o <<= 1) {
            int n = __shfl_up_sync(0xffffffffu, t, o);
            if (lane >= o) t += n;
        }
        wsum[lane] = t;
    }
    __syncthreads();
    int base = (wid > 0) ? wsum[wid - 1] : 0;
    if (i < NN) g_off[i] = base + s - v;
    if (threadIdx.x == 1023) g_part[blockIdx.x] = base + s;
}
__global__ void scan2_k() {
    int run = 0;
    for (int c = 0; c < NCHUNK; c++) { int v = g_part[c]; g_part[c] = run; run += v; }
    g_off[NN] = run;
}
__global__ void scan3_k() {
    int i = blockIdx.x * 1024 + threadIdx.x;
    if (i < NN) g_off[i] += g_part[blockIdx.x];
}
__global__ void scatter_k(const int* __restrict__ src, const int* __restrict__ dst,
                          const float* __restrict__ w) {
    int e = blockIdx.x * blockDim.x + threadIdx.x;
    if (e >= EE) return;
    int d = dst[e];
    int p = g_off[d] + atomicAdd(&g_cur[d], 1);
    g_src_s[p] = src[e];
    g_w_s[p]   = w[e];
}

// ================= hi/lo bf16 store =================
__device__ __forceinline__ void store_hilo(size_t idx, float4 f) {
    __nv_bfloat16 hx = __float2bfloat16_rn(f.x);
    __nv_bfloat16 hy = __float2bfloat16_rn(f.y);
    __nv_bfloat16 hz = __float2bfloat16_rn(f.z);
    __nv_bfloat16 hw = __float2bfloat16_rn(f.w);
    __nv_bfloat16 lx = __float2bfloat16_rn(f.x - __bfloat162float(hx));
    __nv_bfloat16 ly = __float2bfloat16_rn(f.y - __bfloat162float(hy));
    __nv_bfloat16 lz = __float2bfloat16_rn(f.z - __bfloat162float(hz));
    __nv_bfloat16 lw = __float2bfloat16_rn(f.w - __bfloat162float(hw));
    union { __nv_bfloat16 h[4]; uint2 u; } ph, pl;
    ph.h[0] = hx; ph.h[1] = hy; ph.h[2] = hz; ph.h[3] = hw;
    pl.h[0] = lx; pl.h[1] = ly; pl.h[2] = lz; pl.h[3] = lw;
    *reinterpret_cast<uint2*>(&g_fh[idx]) = ph.u;
    *reinterpret_cast<uint2*>(&g_fl[idx]) = pl.u;
}

// ================= layer prep =================
__global__ void prep_k(const float* __restrict__ in) {
    int idx = blockIdx.x * blockDim.x + threadIdx.x;   // N*32
    if (idx >= NN * 32) return;
    int n = idx >> 5, q = idx & 31;
    float4 v = *reinterpret_cast<const float4*>(&in[(size_t)n * 128 + q * 4]);
    store_hilo((size_t)n * 512 + q * 4, v);
    float dn = g_deg_norm[n];
    g_rs_a[idx] = make_float4(v.x * dn, v.y * dn, v.z * dn, v.w * dn);
}

// ================= hop =================
__global__ void hop_k(const float4* __restrict__ rs_in, float4* __restrict__ rs_out,
                      int colofs) {
    int gid = blockIdx.x * blockDim.x + threadIdx.x;
    int node = gid >> 5;
    int lane = gid & 31;
    if (node >= NN) return;
    int beg = g_off[node], end = g_off[node + 1];
    float4 acc = make_float4(0.f, 0.f, 0.f, 0.f);
    int e = beg;
    for (; e + 1 < end; e += 2) {
        int   s0 = g_src_s[e];     float w0 = g_w_s[e];
        int   s1 = g_src_s[e + 1]; float w1 = g_w_s[e + 1];
        float4 v0 = rs_in[(size_t)s0 * 32 + lane];
        float4 v1 = rs_in[(size_t)s1 * 32 + lane];
        acc.x = fmaf(w0, v0.x, acc.x); acc.y = fmaf(w0, v0.y, acc.y);
        acc.z = fmaf(w0, v0.z, acc.z); acc.w = fmaf(w0, v0.w, acc.w);
        acc.x = fmaf(w1, v1.x, acc.x); acc.y = fmaf(w1, v1.y, acc.y);
        acc.z = fmaf(w1, v1.z, acc.z); acc.w = fmaf(w1, v1.w, acc.w);
    }
    if (e < end) {
        int s = g_src_s[e]; float w = g_w_s[e];
        float4 v = rs_in[(size_t)s * 32 + lane];
        acc.x = fmaf(w, v.x, acc.x); acc.y = fmaf(w, v.y, acc.y);
        acc.z = fmaf(w, v.z, acc.z); acc.w = fmaf(w, v.w, acc.w);
    }
    float dn = g_deg_norm[node];
    float4 f = make_float4(dn * acc.x, dn * acc.y, dn * acc.z, dn * acc.w);
    store_hilo((size_t)node * 512 + colofs + lane * 4, f);
    rs_out[(size_t)node * 32 + lane] =
        make_float4(dn * f.x, dn * f.y, dn * f.z, dn * f.w);
}

// ================= W transpose + hi/lo split =================
__global__ void convw_k(const float* __restrict__ W, int ncols, int layer) {
    int i = blockIdx.x * blockDim.x + threadIdx.x;
    if (i >= 512 * ncols) return;
    int k = i / ncols, n = i % ncols;
    float v = W[i];
    __nv_bfloat16 h = __float2bfloat16_rn(v);
    __nv_bfloat16 l = __float2bfloat16_rn(v - __bfloat162float(h));
    g_wh[layer][(size_t)n * 512 + k] = h;
    g_wl[layer][(size_t)n * 512 + k] = l;
}

// ================= HMMA GEMM: C[M,LDC] = fcat[M,512] @ W[512,LDC] + bias =================
// 3-pass hi/lo bf16 (AhBh + AhBl + AlBh), fp32 accumulate via mma.sync m16n8k16.
// Block: 256 threads, BM=128, BN=64 (blockIdx.y selects n-half when LDC=128).
template <int LDC, bool RELU>
__global__ __launch_bounds__(256)
void hmma_gemm_k(const float* __restrict__ bias, float* __restrict__ C, int M, int layer) {
    constexpr int PAD = 40;   // row stride in bf16 (32 data + 8 pad)
    __shared__ __align__(16) __nv_bfloat16 sA[2][128 * PAD];
    __shared__ __align__(16) __nv_bfloat16 sB[2][64 * PAD];

    int t = threadIdx.x;
    int wid = t >> 5, lane = t & 31;
    int wm = wid & 3, wn = wid >> 2;      // 4 x 2 warps, warp tile 32x32
    int row0 = blockIdx.x * 128;
    int nbase = blockIdx.y * 64;

    const __nv_bfloat16* Bh = g_wh[layer];
    const __nv_bfloat16* Bl = g_wl[layer];

    float acc[2][4][4];
    #pragma unroll
    for (int i = 0; i < 2; i++)
        #pragma unroll
        for (int j = 0; j < 4; j++)
            #pragma unroll
            for (int q = 0; q < 4; q++) acc[i][j][q] = 0.f;

    for (int kc = 0; kc < 16; kc++) {
        int k0 = kc * 32;
        // --- load A hi/lo: 128 rows x 32 cols, 512 uint4 per matrix ---
        #pragma unroll
        for (int m = 0; m < 2; m++) {
            const __nv_bfloat16* srcm = m ? g_fl : g_fh;
            #pragma unroll
            for (int l = 0; l < 2; l++) {
                int idx = t + l * 256;            // 0..511
                int r = idx >> 2, g = idx & 3;
                int gr = row0 + r;
                uint4 v = make_uint4(0, 0, 0, 0);
                if (gr < M)
                    v = *reinterpret_cast<const uint4*>(&srcm[(size_t)gr * 512 + k0 + g * 8]);
                *reinterpret_cast<uint4*>(&sA[m][r * PAD + g * 8]) = v;
            }
        }
        // --- load B hi/lo: 64 rows x 32 cols, 256 uint4 per matrix ---
        {
            int idx = t;                          // 0..255
            int r = idx >> 2, g = idx & 3;
            size_t go = (size_t)(nbase + r) * 512 + k0 + g * 8;
            *reinterpret_cast<uint4*>(&sB[0][r * PAD + g * 8]) =
                *reinterpret_cast<const uint4*>(&Bh[go]);
            *reinterpret_cast<uint4*>(&sB[1][r * PAD + g * 8]) =
                *reinterpret_cast<const uint4*>(&Bl[go]);
        }
        __syncthreads();

        #pragma unroll
        for (int k16 = 0; k16 < 2; k16++) {
            int colb = k16 * 16 + (lane >> 4) * 8;
            // A fragments (hi, lo) for both 16-row tiles
            uint32_t ah[2][4], al[2][4];
            #pragma unroll
            for (int mt = 0; mt < 2; mt++) {
                int r = wm * 32 + mt * 16 + (lane & 15);
                ldsm4(ah[mt][0], ah[mt][1], ah[mt][2], ah[mt][3],
                      smem_u32(&sA[0][r * PAD + colb]));
                ldsm4(al[mt][0], al[mt][1], al[mt][2], al[mt][3],
                      smem_u32(&sA[1][r * PAD + colb]));
            }
            // B fragments (hi, lo): 4 n8-tiles via 2 x4 loads per matrix
            uint32_t bh[4][2], bl[4][2];
            #pragma unroll
            for (int np = 0; np < 2; np++) {
                int r = wn * 32 + np * 16 + (lane & 15);
                uint32_t r0, r1, r2, r3;
                ldsm4(r0, r1, r2, r3, smem_u32(&sB[0][r * PAD + colb]));
                bh[np * 2 + 0][0] = r0; bh[np * 2 + 0][1] = r2;
                bh[np * 2 + 1][0] = r1; bh[np * 2 + 1][1] = r3;
                ldsm4(r0, r1, r2, r3, smem_u32(&sB[1][r * PAD + colb]));
                bl[np * 2 + 0][0] = r0; bl[np * 2 + 0][1] = r2;
                bl[np * 2 + 1][0] = r1; bl[np * 2 + 1][1] = r3;
            }
            #pragma unroll
            for (int mt = 0; mt < 2; mt++)
                #pragma unroll
                for (int nt = 0; nt < 4; nt++) {
                    mma16816(acc[mt][nt], ah[mt], bh[nt]);
                    mma16816(acc[mt][nt], ah[mt], bl[nt]);
                    mma16816(acc[mt][nt], al[mt], bh[nt]);
                }
        }
        __syncthreads();
    }

    // --- epilogue ---
    #pragma unroll
    for (int mt = 0; mt < 2; mt++) {
        int r_lo = row0 + wm * 32 + mt * 16 + (lane >> 2);
        #pragma unroll
        for (int nt = 0; nt < 4; nt++) {
            int col = nbase + wn * 32 + nt * 8 + (lane & 3) * 2;
            float b0 = bias[col], b1 = bias[col + 1];
            float v0 = acc[mt][nt][0] + b0;
            float v1 = acc[mt][nt][1] + b1;
            float v2 = acc[mt][nt][2] + b0;
            float v3 = acc[mt][nt][3] + b1;
            if (RELU) {
                v0 = fmaxf(v0, 0.f); v1 = fmaxf(v1, 0.f);
                v2 = fmaxf(v2, 0.f); v3 = fmaxf(v3, 0.f);
            }
            if (r_lo < M)
                *reinterpret_cast<float2*>(&C[(size_t)r_lo * LDC + col]) =
                    make_float2(v0, v1);
            if (r_lo + 8 < M)
                *reinterpret_cast<float2*>(&C[(size_t)(r_lo + 8) * LDC + col]) =
                    make_float2(v2, v3);
        }
    }
}

// ================= predictor =================
__global__ __launch_bounds__(256)
void pred_k(const int* __restrict__ pa, const int* __restrict__ pb,
            const int* __restrict__ na, const int* __restrict__ nb,
            const float* __restrict__ h,
            const float* __restrict__ P1, const float* __restrict__ pb1,
            const float* __restrict__ P2, const float* __restrict__ pb2,
            const float* __restrict__ P3, const float* __restrict__ pb3,
            float* __restrict__ out) {
    __shared__ float sP1[64 * 32];
    __shared__ float sP2[32 * 16];
    __shared__ float sP3[16];
    __shared__ float sb1[32];
    __shared__ float sb2[16];
    __shared__ float sb3;
    __shared__ float sz[8][64];
    int t = threadIdx.x;
    for (int i = t; i < 2048; i += 256) sP1[i] = P1[i];
    for (int i = t; i < 512; i += 256) sP2[i] = P2[i];
    if (t < 16) sP3[t] = P3[t];
    if (t < 32) sb1[t] = pb1[t];
    if (t < 16) sb2[t] = pb2[t];
    if (t == 0) sb3 = pb3[0];
    __syncthreads();
    int w = t >> 5, lane = t & 31;
    int gw = blockIdx.x * 8 + w;
    int nwarps = gridDim.x * 8;
    for (int p = gw; p < 2 * PP; p += nwarps) {
        int a, b;
        if (p < PP) { a = pa[p]; b = pb[p]; }
        else        { a = na[p - PP]; b = nb[p - PP]; }
        float2 ha = *reinterpret_cast<const float2*>(&h[(size_t)a * 64 + lane * 2]);
        float2 hb = *reinterpret_cast<const float2*>(&h[(size_t)b * 64 + lane * 2]);
        sz[w][lane * 2]     = ha.x * hb.x;
        sz[w][lane * 2 + 1] = ha.y * hb.y;
        __syncwarp();
        float acc = sb1[lane];
        #pragma unroll
        for (int i = 0; i < 64; i++) acc = fmaf(sz[w][i], sP1[i * 32 + lane], acc);
        acc = acc > 0.f ? acc : 0.2f * acc;
        __syncwarp();
        sz[w][lane] = acc;
        __syncwarp();
        float acc2 = 0.f;
        if (lane < 16) {
            acc2 = sb2[lane];
            #pragma unroll
            for (int i = 0; i < 32; i++) acc2 = fmaf(sz[w][i], sP2[i * 16 + lane], acc2);
            acc2 = acc2 > 0.f ? acc2 : 0.2f * acc2;
        }
        __syncwarp();
        if (lane < 16) sz[w][lane] = acc2 * sP3[lane];
        __syncwarp();
        if (lane == 0) {
            float s = sb3;
            #pragma unroll
            for (int i = 0; i < 16; i++) s += sz[w][i];
            out[p] = s;
        }
        __syncwarp();
    }
}

// ================= host launcher =================
extern "C" void kernel_launch(void* const* d_in, const int* in_sizes, int n_in,
                              void* d_out, int out_size) {
    const float* x       = (const float*)d_in[0];
    const int*   src     = (const int*)d_in[1];
    const int*   dst     = (const int*)d_in[2];
    const float* w_edge  = (const float*)d_in[3];
    const int*   pos_src = (const int*)d_in[4];
    const int*   pos_dst = (const int*)d_in[5];
    const int*   neg_src = (const int*)d_in[6];
    const int*   neg_dst = (const int*)d_in[7];
    const float* W1 = (const float*)d_in[8];
    const float* b1 = (const float*)d_in[9];
    const float* W2 = (const float*)d_in[10];
    const float* b2 = (const float*)d_in[11];
    const float* W3 = (const float*)d_in[12];
    const float* b3 = (const float*)d_in[13];
    const float* P1 = (const float*)d_in[14];
    const float* pb1 = (const float*)d_in[15];
    const float* P2 = (const float*)d_in[16];
    const float* pb2 = (const float*)d_in[17];
    const float* P3 = (const float*)d_in[18];
    const float* pb3 = (const float*)d_in[19];

    float* out = (float*)d_out;
    float* out_pos = out;                 // [P],[P],[N,64]
    float* out_h   = out + 2 * PP;

    static float4* rs_a = nullptr;
    static float4* rs_b = nullptr;
    static float*  hbuf = nullptr;
    if (!rs_a) {
        cudaGetSymbolAddress((void**)&rs_a, g_rs_a);
        cudaGetSymbolAddress((void**)&rs_b, g_rs_b);
        cudaGetSymbolAddress((void**)&hbuf, g_h);
    }

    const int TB = 256;
    int nb_N  = (NN + TB - 1) / TB;
    int nb_E  = (EE + TB - 1) / TB;
    int nb_hop = (NN * 32 + TB - 1) / TB;
    int nb_gemm = (NN + 127) / 128;

    // CSR build
    zero_k<<<nb_N, TB>>>();
    count_k<<<nb_E, TB>>>(dst);
    degnorm_k<<<nb_N, TB>>>();
    scan1_k<<<NCHUNK, 1024>>>();
    scan2_k<<<1, 1>>>();
    scan3_k<<<NCHUNK, 1024>>>();
    scatter_k<<<nb_E, TB>>>(src, dst, w_edge);

    // weight transpose + hi/lo split
    convw_k<<<(512 * 128 + TB - 1) / TB, TB>>>(W1, 128, 0);
    convw_k<<<(512 * 128 + TB - 1) / TB, TB>>>(W2, 128, 1);
    convw_k<<<(512 * 64 + TB - 1) / TB, TB>>>(W3, 64, 2);

    // ---- layer 1 ----
    prep_k<<<nb_hop, TB>>>(x);
    hop_k<<<nb_hop, TB>>>(rs_a, rs_b, 128);
    hop_k<<<nb_hop, TB>>>(rs_b, rs_a, 256);
    hop_k<<<nb_hop, TB>>>(rs_a, rs_b, 384);
    hmma_gemm_k<128, true><<<dim3(nb_gemm, 2), 256>>>(b1, hbuf, NN, 0);

    // ---- layer 2 ----
    prep_k<<<nb_hop, TB>>>(hbuf);
    hop_k<<<nb_hop, TB>>>(rs_a, rs_b, 128);
    hop_k<<<nb_hop, TB>>>(rs_b, rs_a, 256);
    hop_k<<<nb_hop, TB>>>(rs_a, rs_b, 384);
    hmma_gemm_k<128, true><<<dim3(nb_gemm, 2), 256>>>(b2, hbuf, NN, 1);

    // ---- layer 3 ----
    prep_k<<<nb_hop, TB>>>(hbuf);
    hop_k<<<nb_hop, TB>>>(rs_a, rs_b, 128);
    hop_k<<<nb_hop, TB>>>(rs_b, rs_a, 256);
    hop_k<<<nb_hop, TB>>>(rs_a, rs_b, 384);
    hmma_gemm_k<64, false><<<dim3(nb_gemm, 1), 256>>>(b3, out_h, NN, 2);

    // ---- predictor (pos+neg fused) ----
    pred_k<<<1024, 256>>>(pos_src, pos_dst, neg_src, neg_dst, out_h,
                          P1, pb1, P2, pb2, P3, pb3, out_pos);
}

// round 12
// speedup vs baseline: 1.5971x; 1.0821x over previous
#include <cuda_runtime.h>
#include <cuda_bf16.h>
#include <cstdint>

#define NN 50000
#define EE 800000
#define PP 65536
#define NCHUNK ((NN + 1023) / 1024)

// ================= device scratch =================
__device__ int    g_cnt[NN];
__device__ int    g_cur[NN];
__device__ int    g_off[NN + 1];
__device__ int    g_part[NCHUNK];
__device__ float  g_deg_norm[NN];
__device__ int    g_src_s[EE];
__device__ float  g_w_s[EE];
__device__ __nv_bfloat16 g_fh[(size_t)NN * 512];   // concat hi [N,512]
__device__ __nv_bfloat16 g_fl[(size_t)NN * 512];   // concat lo [N,512]
__device__ float  g_h[(size_t)NN * 128];           // layer output [N,128]
__device__ float4 g_rs_a[(size_t)NN * 32];
__device__ float4 g_rs_b[(size_t)NN * 32];
__device__ __nv_bfloat16 g_wh[3][128 * 512];       // W^T hi per layer [n,k]
__device__ __nv_bfloat16 g_wl[3][128 * 512];       // W^T lo per layer [n,k]

// ================= small helpers =================
__device__ __forceinline__ uint32_t smem_u32(const void* p) {
    uint32_t a;
    asm("{ .reg .u64 t; cvta.to.shared.u64 t, %1; cvt.u32.u64 %0, t; }" : "=r"(a) : "l"(p));
    return a;
}
__device__ __forceinline__ void ldsm4(uint32_t& r0, uint32_t& r1, uint32_t& r2,
                                      uint32_t& r3, uint32_t addr) {
    asm volatile("ldmatrix.sync.aligned.m8n8.x4.shared.b16 {%0,%1,%2,%3}, [%4];"
                 : "=r"(r0), "=r"(r1), "=r"(r2), "=r"(r3) : "r"(addr));
}
__device__ __forceinline__ void mma16816(float* c, const uint32_t* a, const uint32_t* b) {
    asm volatile(
        "mma.sync.aligned.m16n8k16.row.col.f32.bf16.bf16.f32 "
        "{%0,%1,%2,%3}, {%4,%5,%6,%7}, {%8,%9}, {%0,%1,%2,%3};"
        : "+f"(c[0]), "+f"(c[1]), "+f"(c[2]), "+f"(c[3])
        : "r"(a[0]), "r"(a[1]), "r"(a[2]), "r"(a[3]), "r"(b[0]), "r"(b[1]));
}
__device__ __forceinline__ void cp16(uint32_t saddr, const void* g, bool pred) {
    int sz = pred ? 16 : 0;
    asm volatile("cp.async.cg.shared.global [%0], [%1], 16, %2;"
                 :: "r"(saddr), "l"(g), "r"(sz));
}
__device__ __forceinline__ void cp16u(uint32_t saddr, const void* g) {
    asm volatile("cp.async.cg.shared.global [%0], [%1], 16;" :: "r"(saddr), "l"(g));
}
__device__ __forceinline__ void cp_commit() {
    asm volatile("cp.async.commit_group;" ::: "memory");
}
template <int N>
__device__ __forceinline__ void cp_wait() {
    asm volatile("cp.async.wait_group %0;" :: "n"(N) : "memory");
}

// ================= CSR build =================
__global__ void zero_k() {
    int i = blockIdx.x * blockDim.x + threadIdx.x;
    if (i < NN) { g_cnt[i] = 0; g_cur[i] = 0; }
}
__global__ void count_k(const int* __restrict__ dst) {
    int e = blockIdx.x * blockDim.x + threadIdx.x;
    if (e < EE) atomicAdd(&g_cnt[dst[e]], 1);
}
__global__ void degnorm_k() {
    int i = blockIdx.x * blockDim.x + threadIdx.x;
    if (i < NN) g_deg_norm[i] = rsqrtf(fmaxf((float)g_cnt[i], 1.0f));
}
__global__ void scan1_k() {
    __shared__ int wsum[32];
    int lane = threadIdx.x & 31, wid = threadIdx.x >> 5;
    int i = blockIdx.x * 1024 + threadIdx.x;
    int v = (i < NN) ? g_cnt[i] : 0;
    int s = v;
    #pragma unroll
    for (int o = 1; o < 32; o <<= 1) {
        int n = __shfl_up_sync(0xffffffffu, s, o);
        if (lane >= o) s += n;
    }
    if (lane == 31) wsum[wid] = s;
    __syncthreads();
    if (wid == 0) {
        int t = wsum[lane];
        #pragma unroll
        for (int o = 1; o < 32; o <<= 1) {
            int n = __shfl_up_sync(0xffffffffu, t, o);
            if (lane >= o) t += n;
        }
        wsum[lane] = t;
    }
    __syncthreads();
    int base = (wid > 0) ? wsum[wid - 1] : 0;
    if (i < NN) g_off[i] = base + s - v;
    if (threadIdx.x == 1023) g_part[blockIdx.x] = base + s;
}
__global__ void scan2_k() {
    int run = 0;
    for (int c = 0; c < NCHUNK; c++) { int v = g_part[c]; g_part[c] = run; run += v; }
    g_off[NN] = run;
}
__global__ void scan3_k() {
    int i = blockIdx.x * 1024 + threadIdx.x;
    if (i < NN) g_off[i] += g_part[blockIdx.x];
}
__global__ void scatter_k(const int* __restrict__ src, const int* __restrict__ dst,
                          const float* __restrict__ w) {
    int e = blockIdx.x * blockDim.x + threadIdx.x;
    if (e >= EE) return;
    int d = dst[e];
    int p = g_off[d] + atomicAdd(&g_cur[d], 1);
    g_src_s[p] = src[e];
    g_w_s[p]   = w[e];
}

// ================= hi/lo bf16 store =================
__device__ __forceinline__ void store_hilo(size_t idx, float4 f) {
    __nv_bfloat16 hx = __float2bfloat16_rn(f.x);
    __nv_bfloat16 hy = __float2bfloat16_rn(f.y);
    __nv_bfloat16 hz = __float2bfloat16_rn(f.z);
    __nv_bfloat16 hw = __float2bfloat16_rn(f.w);
    __nv_bfloat16 lx = __float2bfloat16_rn(f.x - __bfloat162float(hx));
    __nv_bfloat16 ly = __float2bfloat16_rn(f.y - __bfloat162float(hy));
    __nv_bfloat16 lz = __float2bfloat16_rn(f.z - __bfloat162float(hz));
    __nv_bfloat16 lw = __float2bfloat16_rn(f.w - __bfloat162float(hw));
    union { __nv_bfloat16 h[4]; uint2 u; } ph, pl;
    ph.h[0] = hx; ph.h[1] = hy; ph.h[2] = hz; ph.h[3] = hw;
    pl.h[0] = lx; pl.h[1] = ly; pl.h[2] = lz; pl.h[3] = lw;
    *reinterpret_cast<uint2*>(&g_fh[idx]) = ph.u;
    *reinterpret_cast<uint2*>(&g_fl[idx]) = pl.u;
}

// ================= layer prep =================
__global__ void prep_k(const float* __restrict__ in) {
    int idx = blockIdx.x * blockDim.x + threadIdx.x;   // N*32
    if (idx >= NN * 32) return;
    int n = idx >> 5, q = idx & 31;
    float4 v = *reinterpret_cast<const float4*>(&in[(size_t)n * 128 + q * 4]);
    store_hilo((size_t)n * 512 + q * 4, v);
    float dn = g_deg_norm[n];
    g_rs_a[idx] = make_float4(v.x * dn, v.y * dn, v.z * dn, v.w * dn);
}

// ================= hop =================
__global__ void hop_k(const float4* __restrict__ rs_in, float4* __restrict__ rs_out,
                      int colofs) {
    int gid = blockIdx.x * blockDim.x + threadIdx.x;
    int node = gid >> 5;
    int lane = gid & 31;
    if (node >= NN) return;
    int beg = g_off[node], end = g_off[node + 1];
    float4 acc = make_float4(0.f, 0.f, 0.f, 0.f);
    int e = beg;
    for (; e + 3 < end; e += 4) {
        int   s0 = g_src_s[e];     float w0 = g_w_s[e];
        int   s1 = g_src_s[e + 1]; float w1 = g_w_s[e + 1];
        int   s2 = g_src_s[e + 2]; float w2 = g_w_s[e + 2];
        int   s3 = g_src_s[e + 3]; float w3 = g_w_s[e + 3];
        float4 v0 = rs_in[(size_t)s0 * 32 + lane];
        float4 v1 = rs_in[(size_t)s1 * 32 + lane];
        float4 v2 = rs_in[(size_t)s2 * 32 + lane];
        float4 v3 = rs_in[(size_t)s3 * 32 + lane];
        acc.x = fmaf(w0, v0.x, acc.x); acc.y = fmaf(w0, v0.y, acc.y);
        acc.z = fmaf(w0, v0.z, acc.z); acc.w = fmaf(w0, v0.w, acc.w);
        acc.x = fmaf(w1, v1.x, acc.x); acc.y = fmaf(w1, v1.y, acc.y);
        acc.z = fmaf(w1, v1.z, acc.z); acc.w = fmaf(w1, v1.w, acc.w);
        acc.x = fmaf(w2, v2.x, acc.x); acc.y = fmaf(w2, v2.y, acc.y);
        acc.z = fmaf(w2, v2.z, acc.z); acc.w = fmaf(w2, v2.w, acc.w);
        acc.x = fmaf(w3, v3.x, acc.x); acc.y = fmaf(w3, v3.y, acc.y);
        acc.z = fmaf(w3, v3.z, acc.z); acc.w = fmaf(w3, v3.w, acc.w);
    }
    for (; e < end; e++) {
        int s = g_src_s[e]; float w = g_w_s[e];
        float4 v = rs_in[(size_t)s * 32 + lane];
        acc.x = fmaf(w, v.x, acc.x); acc.y = fmaf(w, v.y, acc.y);
        acc.z = fmaf(w, v.z, acc.z); acc.w = fmaf(w, v.w, acc.w);
    }
    float dn = g_deg_norm[node];
    float4 f = make_float4(dn * acc.x, dn * acc.y, dn * acc.z, dn * acc.w);
    store_hilo((size_t)node * 512 + colofs + lane * 4, f);
    rs_out[(size_t)node * 32 + lane] =
        make_float4(dn * f.x, dn * f.y, dn * f.z, dn * f.w);
}

// ================= W transpose + hi/lo split =================
__global__ void convw_k(const float* __restrict__ W, int ncols, int layer) {
    int i = blockIdx.x * blockDim.x + threadIdx.x;
    if (i >= 512 * ncols) return;
    int k = i / ncols, n = i % ncols;
    float v = W[i];
    __nv_bfloat16 h = __float2bfloat16_rn(v);
    __nv_bfloat16 l = __float2bfloat16_rn(v - __bfloat162float(h));
    g_wh[layer][(size_t)n * 512 + k] = h;
    g_wl[layer][(size_t)n * 512 + k] = l;
}

// ================= HMMA GEMM (double-buffered cp.async) =================
// C[M,BN] = fcat[M,512] @ W[512,BN] + bias.  3-pass hi/lo bf16, fp32 accum.
// 256 thr, BM=128, BN full output width. Warps 4(m) x 2(n), warp tile 32 x BN/2.
template <int BN, bool RELU>
__global__ __launch_bounds__(256, 2)
void hmma_gemm_k(const float* __restrict__ bias, float* __restrict__ C, int M, int layer) {
    constexpr int PAD = 40;               // bf16 row stride (32 data + 8 pad)
    constexpr int A_MAT = 128 * PAD;      // elems per A matrix buffer
    constexpr int B_MAT = BN * PAD;
    constexpr int NT = BN / 16;           // n8 tiles per warp
    constexpr int NP = NT / 2;            // 16-row ldsm groups per warp
    constexpr int NB_LD = BN * 8 / 256;   // B uint4 loads per thread per stage
    extern __shared__ __nv_bfloat16 sm[];

    int t = threadIdx.x;
    int wid = t >> 5, lane = t & 31;
    int wm = wid & 3, wn = wid >> 2;
    int row0 = blockIdx.x * 128;

    const __nv_bfloat16* Bh = g_wh[layer];
    const __nv_bfloat16* Bl = g_wl[layer];

    // smem region helpers (element offsets)
    auto sAo = [&](int buf, int mat) { return (buf * 2 + mat) * A_MAT; };
    auto sBo = [&](int buf, int mat) { return 4 * A_MAT + (buf * 2 + mat) * B_MAT; };
    uint32_t smb = smem_u32(sm);

    // ---- stage prefetch ----
    auto prefetch = [&](int kc, int buf) {
        int k0 = kc * 32;
        // A hi/lo: 1024 uint4 -> 4 per thread
        #pragma unroll
        for (int l = 0; l < 4; l++) {
            int idx = t + l * 256;
            int mat = idx >> 9, rem = idx & 511;
            int r = rem >> 2, g = rem & 3;
            int gr = row0 + r;
            const __nv_bfloat16* srcm = mat ? g_fl : g_fh;
            cp16(smb + (sAo(buf, mat) + r * PAD + g * 8) * 2,
                 &srcm[(size_t)gr * 512 + k0 + g * 8], gr < M);
        }
        // B hi/lo: BN*8 uint4 -> NB_LD per thread
        #pragma unroll
        for (int l = 0; l < NB_LD; l++) {
            int idx = t + l * 256;
            int mat = idx / (BN * 4), rem = idx % (BN * 4);
            int r = rem >> 2, g = rem & 3;
            const __nv_bfloat16* srcm = mat ? Bl : Bh;
            cp16u(smb + (sBo(buf, mat) + r * PAD + g * 8) * 2,
                  &srcm[(size_t)r * 512 + k0 + g * 8]);
        }
        cp_commit();
    };

    float acc[2][NT][4];
    #pragma unroll
    for (int i = 0; i < 2; i++)
        #pragma unroll
        for (int j = 0; j < NT; j++)
            #pragma unroll
            for (int q = 0; q < 4; q++) acc[i][j][q] = 0.f;

    prefetch(0, 0);

    for (int kc = 0; kc < 16; kc++) {
        int buf = kc & 1;
        if (kc + 1 < 16) prefetch(kc + 1, (kc + 1) & 1);
        if (kc + 1 < 16) cp_wait<1>(); else cp_wait<0>();
        __syncthreads();

        #pragma unroll
        for (int k16 = 0; k16 < 2; k16++) {
            int colb = k16 * 16 + (lane >> 4) * 8;
            uint32_t ah[2][4], al[2][4];
            #pragma unroll
            for (int mt = 0; mt < 2; mt++) {
                int r = wm * 32 + mt * 16 + (lane & 15);
                ldsm4(ah[mt][0], ah[mt][1], ah[mt][2], ah[mt][3],
                      smb + (sAo(buf, 0) + r * PAD + colb) * 2);
                ldsm4(al[mt][0], al[mt][1], al[mt][2], al[mt][3],
                      smb + (sAo(buf, 1) + r * PAD + colb) * 2);
            }
            #pragma unroll
            for (int np = 0; np < NP; np++) {
                int r = wn * (BN / 2) + np * 16 + (lane & 15);
                uint32_t h0, h1, h2, h3, l0, l1, l2, l3;
                ldsm4(h0, h1, h2, h3, smb + (sBo(buf, 0) + r * PAD + colb) * 2);
                ldsm4(l0, l1, l2, l3, smb + (sBo(buf, 1) + r * PAD + colb) * 2);
                uint32_t bh0[2] = {h0, h2}, bh1[2] = {h1, h3};
                uint32_t bl0[2] = {l0, l2}, bl1[2] = {l1, l3};
                #pragma unroll
                for (int mt = 0; mt < 2; mt++) {
                    mma16816(acc[mt][np * 2 + 0], ah[mt], bh0);
                    mma16816(acc[mt][np * 2 + 0], ah[mt], bl0);
                    mma16816(acc[mt][np * 2 + 0], al[mt], bh0);
                    mma16816(acc[mt][np * 2 + 1], ah[mt], bh1);
                    mma16816(acc[mt][np * 2 + 1], ah[mt], bl1);
                    mma16816(acc[mt][np * 2 + 1], al[mt], bh1);
                }
            }
        }
        __syncthreads();
    }

    // ---- epilogue ----
    #pragma unroll
    for (int mt = 0; mt < 2; mt++) {
        int r_lo = row0 + wm * 32 + mt * 16 + (lane >> 2);
        #pragma unroll
        for (int nt = 0; nt < NT; nt++) {
            int col = wn * (BN / 2) + nt * 8 + (lane & 3) * 2;
            float b0 = bias[col], b1 = bias[col + 1];
            float v0 = acc[mt][nt][0] + b0;
            float v1 = acc[mt][nt][1] + b1;
            float v2 = acc[mt][nt][2] + b0;
            float v3 = acc[mt][nt][3] + b1;
            if (RELU) {
                v0 = fmaxf(v0, 0.f); v1 = fmaxf(v1, 0.f);
                v2 = fmaxf(v2, 0.f); v3 = fmaxf(v3, 0.f);
            }
            if (r_lo < M)
                *reinterpret_cast<float2*>(&C[(size_t)r_lo * BN + col]) =
                    make_float2(v0, v1);
            if (r_lo + 8 < M)
                *reinterpret_cast<float2*>(&C[(size_t)(r_lo + 8) * BN + col]) =
                    make_float2(v2, v3);
        }
    }
}

// ================= predictor =================
__global__ __launch_bounds__(256)
void pred_k(const int* __restrict__ pa, const int* __restrict__ pb,
            const int* __restrict__ na, const int* __restrict__ nb,
            const float* __restrict__ h,
            const float* __restrict__ P1, const float* __restrict__ pb1,
            const float* __restrict__ P2, const float* __restrict__ pb2,
            const float* __restrict__ P3, const float* __restrict__ pb3,
            float* __restrict__ out) {
    __shared__ float sP1[64 * 32];
    __shared__ float sP2[32 * 16];
    __shared__ float sP3[16];
    __shared__ float sb1[32];
    __shared__ float sb2[16];
    __shared__ float sb3;
    __shared__ float sz[8][64];
    int t = threadIdx.x;
    for (int i = t; i < 2048; i += 256) sP1[i] = P1[i];
    for (int i = t; i < 512; i += 256) sP2[i] = P2[i];
    if (t < 16) sP3[t] = P3[t];
    if (t < 32) sb1[t] = pb1[t];
    if (t < 16) sb2[t] = pb2[t];
    if (t == 0) sb3 = pb3[0];
    __syncthreads();
    int w = t >> 5, lane = t & 31;
    int gw = blockIdx.x * 8 + w;
    int nwarps = gridDim.x * 8;
    for (int p = gw; p < 2 * PP; p += nwarps) {
        int a, b;
        if (p < PP) { a = pa[p]; b = pb[p]; }
        else        { a = na[p - PP]; b = nb[p - PP]; }
        float2 ha = *reinterpret_cast<const float2*>(&h[(size_t)a * 64 + lane * 2]);
        float2 hb = *reinterpret_cast<const float2*>(&h[(size_t)b * 64 + lane * 2]);
        sz[w][lane * 2]     = ha.x * hb.x;
        sz[w][lane * 2 + 1] = ha.y * hb.y;
        __syncwarp();
        float acc = sb1[lane];
        #pragma unroll
        for (int i = 0; i < 64; i++) acc = fmaf(sz[w][i], sP1[i * 32 + lane], acc);
        acc = acc > 0.f ? acc : 0.2f * acc;
        __syncwarp();
        sz[w][lane] = acc;
        __syncwarp();
        float acc2 = 0.f;
        if (lane < 16) {
            acc2 = sb2[lane];
            #pragma unroll
            for (int i = 0; i < 32; i++) acc2 = fmaf(sz[w][i], sP2[i * 16 + lane], acc2);
            acc2 = acc2 > 0.f ? acc2 : 0.2f * acc2;
        }
        __syncwarp();
        if (lane < 16) sz[w][lane] = acc2 * sP3[lane];
        __syncwarp();
        if (lane == 0) {
            float s = sb3;
            #pragma unroll
            for (int i = 0; i < 16; i++) s += sz[w][i];
            out[p] = s;
        }
        __syncwarp();
    }
}

// ================= host launcher =================
extern "C" void kernel_launch(void* const* d_in, const int* in_sizes, int n_in,
                              void* d_out, int out_size) {
    const float* x       = (const float*)d_in[0];
    const int*   src     = (const int*)d_in[1];
    const int*   dst     = (const int*)d_in[2];
    const float* w_edge  = (const float*)d_in[3];
    const int*   pos_src = (const int*)d_in[4];
    const int*   pos_dst = (const int*)d_in[5];
    const int*   neg_src = (const int*)d_in[6];
    const int*   neg_dst = (const int*)d_in[7];
    const float* W1 = (const float*)d_in[8];
    const float* b1 = (const float*)d_in[9];
    const float* W2 = (const float*)d_in[10];
    const float* b2 = (const float*)d_in[11];
    const float* W3 = (const float*)d_in[12];
    const float* b3 = (const float*)d_in[13];
    const float* P1 = (const float*)d_in[14];
    const float* pb1 = (const float*)d_in[15];
    const float* P2 = (const float*)d_in[16];
    const float* pb2 = (const float*)d_in[17];
    const float* P3 = (const float*)d_in[18];
    const float* pb3 = (const float*)d_in[19];

    float* out = (float*)d_out;
    float* out_pos = out;                 // [P],[P],[N,64]
    float* out_h   = out + 2 * PP;

    // smem: 2 bufs x 2 mats x (128 + BN) rows x 40 elems x 2B
    constexpr int SMEM128 = (4 * 128 * 40 + 4 * 128 * 40) * 2;   // 81920
    constexpr int SMEM64  = (4 * 128 * 40 + 4 * 64 * 40) * 2;    // 61440

    static float4* rs_a = nullptr;
    static float4* rs_b = nullptr;
    static float*  hbuf = nullptr;
    if (!rs_a) {
        cudaGetSymbolAddress((void**)&rs_a, g_rs_a);
        cudaGetSymbolAddress((void**)&rs_b, g_rs_b);
        cudaGetSymbolAddress((void**)&hbuf, g_h);
        cudaFuncSetAttribute(hmma_gemm_k<128, true>,
                             cudaFuncAttributeMaxDynamicSharedMemorySize, SMEM128);
        cudaFuncSetAttribute(hmma_gemm_k<64, false>,
                             cudaFuncAttributeMaxDynamicSharedMemorySize, SMEM64);
    }

    const int TB = 256;
    int nb_N  = (NN + TB - 1) / TB;
    int nb_E  = (EE + TB - 1) / TB;
    int nb_hop = (NN * 32 + TB - 1) / TB;
    int nb_gemm = (NN + 127) / 128;

    // CSR build
    zero_k<<<nb_N, TB>>>();
    count_k<<<nb_E, TB>>>(dst);
    degnorm_k<<<nb_N, TB>>>();
    scan1_k<<<NCHUNK, 1024>>>();
    scan2_k<<<1, 1>>>();
    scan3_k<<<NCHUNK, 1024>>>();
    scatter_k<<<nb_E, TB>>>(src, dst, w_edge);

    // weight transpose + hi/lo split
    convw_k<<<(512 * 128 + TB - 1) / TB, TB>>>(W1, 128, 0);
    convw_k<<<(512 * 128 + TB - 1) / TB, TB>>>(W2, 128, 1);
    convw_k<<<(512 * 64 + TB - 1) / TB, TB>>>(W3, 64, 2);

    // ---- layer 1 ----
    prep_k<<<nb_hop, TB>>>(x);
    hop_k<<<nb_hop, TB>>>(rs_a, rs_b, 128);
    hop_k<<<nb_hop, TB>>>(rs_b, rs_a, 256);
    hop_k<<<nb_hop, TB>>>(rs_a, rs_b, 384);
    hmma_gemm_k<128, true><<<nb_gemm, 256, SMEM128>>>(b1, hbuf, NN, 0);

    // ---- layer 2 ----
    prep_k<<<nb_hop, TB>>>(hbuf);
    hop_k<<<nb_hop, TB>>>(rs_a, rs_b, 128);
    hop_k<<<nb_hop, TB>>>(rs_b, rs_a, 256);
    hop_k<<<nb_hop, TB>>>(rs_a, rs_b, 384);
    hmma_gemm_k<128, true><<<nb_gemm, 256, SMEM128>>>(b2, hbuf, NN, 1);

    // ---- layer 3 ----
    prep_k<<<nb_hop, TB>>>(hbuf);
    hop_k<<<nb_hop, TB>>>(rs_a, rs_b, 128);
    hop_k<<<nb_hop, TB>>>(rs_b, rs_a, 256);
    hop_k<<<nb_hop, TB>>>(rs_a, rs_b, 384);
    hmma_gemm_k<64, false><<<nb_gemm, 256, SMEM64>>>(b3, out_h, NN, 2);

    // ---- predictor (pos+neg fused) ----
    pred_k<<<1024, 256>>>(pos_src, pos_dst, neg_src, neg_dst, out_h,
                          P1, pb1, P2, pb2, P3, pb3, out_pos);
}